// round 3
// baseline (speedup 1.0000x reference)
#include <cuda_runtime.h>
#include <cstdint>

// Per-sample dynamic-filter 3x3 VALID conv as implicit GEMM:
//   D[x=128, cout=128] += sum_{ky,kx,ci} X[b, y+ky, x+kx, ci] * W[b, ky, kx, ci, cout]
// mma.sync m16n8k8 tf32 (sm_80+ PTX -> works at compute_103; tcgen05 is NOT
// available in this build's PTX target).

#define OH 126
#define CIN 128
#define COUT 128

// SMEM: A[128 rows(x)][36 floats] (32 ci + pad4), B[32 rows(ci)][136 floats] (128 cout + pad8)
#define A_STRIDE 36
#define B_STRIDE 136

static __device__ __forceinline__ uint32_t f2tf32(float x) {
    uint32_t r;
    asm("cvt.rna.tf32.f32 %0, %1;" : "=r"(r) : "f"(x));
    return r;
}

static __device__ __forceinline__ void mma_tf32(float* c, const uint32_t* a,
                                                uint32_t b0, uint32_t b1) {
    asm volatile(
        "mma.sync.aligned.m16n8k8.row.col.f32.tf32.tf32.f32 "
        "{%0,%1,%2,%3}, {%4,%5,%6,%7}, {%8,%9}, {%0,%1,%2,%3};"
        : "+f"(c[0]), "+f"(c[1]), "+f"(c[2]), "+f"(c[3])
        : "r"(a[0]), "r"(a[1]), "r"(a[2]), "r"(a[3]), "r"(b0), "r"(b1));
}

__global__ void __launch_bounds__(256, 2) conv_mma_kernel(
    const float* __restrict__ X,    // [16,128,128,128]
    const float* __restrict__ Wt,   // [16,3,3,128,128]
    float* __restrict__ Out)        // [16,126,126,128]
{
    __shared__ uint32_t sA[128 * A_STRIDE];   // 18432 B
    __shared__ uint32_t sB[32 * B_STRIDE];    // 17408 B

    const int tid  = threadIdx.x;
    const int lane = tid & 31;
    const int warp = tid >> 5;
    const int wm   = warp & 3;     // warp tile row:  wm*32
    const int wn   = warp >> 2;    // warp tile col:  wn*64
    const int y = blockIdx.x;      // output row 0..125
    const int b = blockIdx.y;      // sample   0..15

    const float* Xb = X  + (size_t)b * (128u * 128u * 128u);
    const float* Wb = Wt + (size_t)b * (9u * 128u * 128u);

    float acc[2][8][4];
    #pragma unroll
    for (int mi = 0; mi < 2; mi++)
        #pragma unroll
        for (int ni = 0; ni < 8; ni++)
            #pragma unroll
            for (int j = 0; j < 4; j++) acc[mi][ni][j] = 0.0f;

    // chunk k -> (ky, c0, kx): ky outer (row slab), kx inner (max X line reuse)
    // k = ky*12 + (c0/32)*3 + kx
    float4 ra[4], rb[4];

    // ---- prefetch chunk 0 ----
    {
        const int ky = 0, kx = 0, c0 = 0;
        const float* Ap = Xb + (size_t)(y + ky) * (128 * 128) + c0;
        #pragma unroll
        for (int t = 0; t < 4; t++) {
            int idx = tid + 256 * t;            // 0..1023 float4s of A
            int r = idx >> 3, s = idx & 7;      // row x, 8 float4 per row
            int xi = r + kx; if (xi > 127) xi = 127;
            ra[t] = *reinterpret_cast<const float4*>(Ap + (size_t)xi * CIN + s * 4);
        }
        const float4* Bp = reinterpret_cast<const float4*>(
            Wb + (size_t)((ky * 3 + kx) * CIN + c0) * COUT);
        #pragma unroll
        for (int t = 0; t < 4; t++) rb[t] = Bp[tid + 256 * t];
    }

    for (int k = 0; k < 36; k++) {
        __syncthreads();   // all warps done computing previous chunk

        // ---- store staged regs -> SMEM (with rna tf32 rounding) ----
        #pragma unroll
        for (int t = 0; t < 4; t++) {
            int idx = tid + 256 * t;
            int r = idx >> 3, s = idx & 7;
            uint32_t* p = &sA[r * A_STRIDE + s * 4];
            p[0] = f2tf32(ra[t].x); p[1] = f2tf32(ra[t].y);
            p[2] = f2tf32(ra[t].z); p[3] = f2tf32(ra[t].w);
        }
        #pragma unroll
        for (int t = 0; t < 4; t++) {
            int idx = tid + 256 * t;
            int r = idx >> 5, s = idx & 31;     // row ci, 32 float4 per row
            uint32_t* p = &sB[r * B_STRIDE + s * 4];
            p[0] = f2tf32(rb[t].x); p[1] = f2tf32(rb[t].y);
            p[2] = f2tf32(rb[t].z); p[3] = f2tf32(rb[t].w);
        }

        // ---- prefetch chunk k+1 (latency hides under compute below) ----
        if (k < 35) {
            int kn = k + 1;
            int ky = kn / 12, rem = kn % 12;
            int c0 = (rem / 3) * 32, kx = rem % 3;
            const float* Ap = Xb + (size_t)(y + ky) * (128 * 128) + c0;
            #pragma unroll
            for (int t = 0; t < 4; t++) {
                int idx = tid + 256 * t;
                int r = idx >> 3, s = idx & 7;
                int xi = r + kx; if (xi > 127) xi = 127;
                ra[t] = *reinterpret_cast<const float4*>(Ap + (size_t)xi * CIN + s * 4);
            }
            const float4* Bp = reinterpret_cast<const float4*>(
                Wb + (size_t)((ky * 3 + kx) * CIN + c0) * COUT);
            #pragma unroll
            for (int t = 0; t < 4; t++) rb[t] = Bp[tid + 256 * t];
        }

        __syncthreads();   // staged data visible

        // ---- compute: 4 k-steps of m16n8k8 over the 32-ci chunk ----
        #pragma unroll
        for (int kk = 0; kk < 4; kk++) {
            const int k0 = kk * 8;
            uint32_t af[2][4];
            const int ar = wm * 32 + (lane >> 2);
            const int ac = k0 + (lane & 3);
            #pragma unroll
            for (int mi = 0; mi < 2; mi++) {
                af[mi][0] = sA[(ar + mi * 16    ) * A_STRIDE + ac    ];
                af[mi][1] = sA[(ar + mi * 16 + 8) * A_STRIDE + ac    ];
                af[mi][2] = sA[(ar + mi * 16    ) * A_STRIDE + ac + 4];
                af[mi][3] = sA[(ar + mi * 16 + 8) * A_STRIDE + ac + 4];
            }
            const int br = k0 + (lane & 3);
            const int bc = wn * 64 + (lane >> 2);
            #pragma unroll
            for (int ni = 0; ni < 8; ni++) {
                uint32_t b0 = sB[(br    ) * B_STRIDE + bc + ni * 8];
                uint32_t b1 = sB[(br + 4) * B_STRIDE + bc + ni * 8];
                mma_tf32(acc[0][ni], af[0], b0, b1);
                mma_tf32(acc[1][ni], af[1], b0, b1);
            }
        }
    }

    // ---- epilogue: registers -> Out, skipping dead x rows (>=126) ----
    float* Ob = Out + ((size_t)b * OH + y) * (OH * (size_t)COUT);
    #pragma unroll
    for (int mi = 0; mi < 2; mi++) {
        const int row0 = wm * 32 + mi * 16 + (lane >> 2);
        #pragma unroll
        for (int ni = 0; ni < 8; ni++) {
            const int col = wn * 64 + ni * 8 + 2 * (lane & 3);
            if (row0 < OH) {
                float2 v = make_float2(acc[mi][ni][0], acc[mi][ni][1]);
                *reinterpret_cast<float2*>(Ob + (size_t)row0 * COUT + col) = v;
            }
            if (row0 + 8 < OH) {
                float2 v = make_float2(acc[mi][ni][2], acc[mi][ni][3]);
                *reinterpret_cast<float2*>(Ob + (size_t)(row0 + 8) * COUT + col) = v;
            }
        }
    }
}

extern "C" void kernel_launch(void* const* d_in, const int* in_sizes, int n_in,
                              void* d_out, int out_size) {
    (void)in_sizes; (void)n_in; (void)out_size;
    const float* X  = (const float*)d_in[0];
    const float* Wt = (const float*)d_in[1];
    float* out = (float*)d_out;
    conv_mma_kernel<<<dim3(OH, 16), 256>>>(X, Wt, out);
}